// round 1
// baseline (speedup 1.0000x reference)
#include <cuda_runtime.h>
#include <cuda_bf16.h>
#include <cstdint>

#define Bn 8192
#define Dn 512
#define Kn 64
#define Hn 256
#define SN (Kn*Kn + Dn)   // 4608

__device__ float g_h1[Bn * Hn];
__device__ float g_s [Bn * SN];
__device__ float g_hU[Bn * Kn];
__device__ float g_h2[Bn * Kn];
__device__ float g_x1[Bn * Dn];
__device__ float g_x2[Bn * Dn];

template<int BM, int BN, int BK, int TM, int TN, int BIAS, bool RELU>
__global__ void __launch_bounds__((BM/TM)*(BN/TN))
gemm_k(const float* __restrict__ A, const float* __restrict__ B,
       const float* __restrict__ bias, int bias_ld,
       float* __restrict__ C, int M, int N, int Kd)
{
    constexpr int NT = (BM/TM)*(BN/TN);
    __shared__ float As[BK][BM + 8];
    __shared__ float Bs[BK][BN];

    const int tid = threadIdx.x;
    const int tx  = tid % (BN/TN);
    const int ty  = tid / (BN/TN);
    const int bm  = blockIdx.y * BM;
    const int bn  = blockIdx.x * BN;

    float acc[TM][TN];
#pragma unroll
    for (int i = 0; i < TM; i++)
#pragma unroll
        for (int j = 0; j < TN; j++) acc[i][j] = 0.f;

    const float* Ag = A + (size_t)bm * Kd;
    const float* Bg = B + bn;

    for (int k0 = 0; k0 < Kd; k0 += BK) {
#pragma unroll
        for (int idx = tid; idx < BM*BK/4; idx += NT) {
            int r  = idx / (BK/4);
            int c4 = (idx % (BK/4)) * 4;
            float4 v = *(const float4*)(Ag + (size_t)r * Kd + k0 + c4);
            As[c4+0][r] = v.x; As[c4+1][r] = v.y;
            As[c4+2][r] = v.z; As[c4+3][r] = v.w;
        }
#pragma unroll
        for (int idx = tid; idx < BK*BN/4; idx += NT) {
            int r  = idx / (BN/4);
            int c4 = (idx % (BN/4)) * 4;
            *(float4*)&Bs[r][c4] = *(const float4*)(Bg + (size_t)(k0 + r) * N + c4);
        }
        __syncthreads();

#pragma unroll
        for (int kk = 0; kk < BK; kk++) {
            float a[TM], b[TN];
#pragma unroll
            for (int i = 0; i < TM; i += 4) {
                float4 v = *(const float4*)&As[kk][ty*TM + i];
                a[i] = v.x; a[i+1] = v.y; a[i+2] = v.z; a[i+3] = v.w;
            }
#pragma unroll
            for (int j = 0; j < TN; j += 4) {
                float4 v = *(const float4*)&Bs[kk][tx*TN + j];
                b[j] = v.x; b[j+1] = v.y; b[j+2] = v.z; b[j+3] = v.w;
            }
#pragma unroll
            for (int i = 0; i < TM; i++)
#pragma unroll
                for (int j = 0; j < TN; j++)
                    acc[i][j] = fmaf(a[i], b[j], acc[i][j]);
        }
        __syncthreads();
    }

#pragma unroll
    for (int i = 0; i < TM; i++) {
        const int row = bm + ty*TM + i;
#pragma unroll
        for (int j = 0; j < TN; j += 4) {
            const int col = bn + tx*TN + j;
            float4 v;
            v.x = acc[i][j+0]; v.y = acc[i][j+1];
            v.z = acc[i][j+2]; v.w = acc[i][j+3];
            if (BIAS == 1) {
                float4 bv = *(const float4*)(bias + col);
                v.x += bv.x; v.y += bv.y; v.z += bv.z; v.w += bv.w;
            } else if (BIAS == 2) {
                float4 bv = *(const float4*)(bias + (size_t)row * bias_ld + col);
                v.x += bv.x; v.y += bv.y; v.z += bv.z; v.w += bv.w;
            }
            if (RELU) {
                v.x = fmaxf(v.x, 0.f); v.y = fmaxf(v.y, 0.f);
                v.z = fmaxf(v.z, 0.f); v.w = fmaxf(v.w, 0.f);
            }
            *(float4*)(C + (size_t)row * N + col) = v;
        }
    }
}

__global__ void __launch_bounds__(256)
einsum_k(const float* __restrict__ hU, const float* __restrict__ s,
         float* __restrict__ h2)
{
    __shared__ float hs[4][Kn];
    const int tid = threadIdx.x;
    const int r   = tid / Kn;
    const int j   = tid % Kn;
    const int b   = blockIdx.x * 4 + r;

    hs[r][j] = hU[(size_t)b * Kn + j];
    __syncthreads();

    const float* S = s + (size_t)b * SN + Dn;
    float acc = 0.f;
#pragma unroll
    for (int k = 0; k < Kn; k++)
        acc = fmaf(hs[r][k], S[(size_t)k * Kn + j], acc);
    h2[(size_t)b * Kn + j] = acc;
}

__global__ void __launch_bounds__(256)
outproj_k(const float* __restrict__ x, const float* __restrict__ W,
          const float* __restrict__ b, float* __restrict__ out)
{
    const int warp = (blockIdx.x * blockDim.x + threadIdx.x) >> 5;
    const int lane = threadIdx.x & 31;
    const float4* xr = (const float4*)(x + (size_t)warp * Dn);
    const float4* W4 = (const float4*)W;
    float acc = 0.f;
#pragma unroll
    for (int i = lane; i < Dn/4; i += 32) {
        float4 a = xr[i], w = W4[i];
        acc += a.x*w.x + a.y*w.y + a.z*w.z + a.w*w.w;
    }
#pragma unroll
    for (int o = 16; o; o >>= 1) acc += __shfl_xor_sync(0xFFFFFFFFu, acc, o);
    if (lane == 0) out[warp] = acc + b[0];
}

static void run_layer(const float* xin,
                      const float* U, const float* V,
                      const float* hW1, const float* hb1,
                      const float* hW2, const float* hb2,
                      float* h1, float* s, float* hU, float* h2,
                      float* xout)
{
    gemm_k<64,128,16,4,8,1,true><<<dim3(Hn/128, Bn/64), 256>>>(
        xin, hW1, hb1, 0, h1, Bn, Hn, Dn);

    gemm_k<128,128,16,8,8,1,false><<<dim3(SN/128, Bn/128), 256>>>(
        h1, hW2, hb2, 0, s, Bn, SN, Hn);

    gemm_k<64,64,16,4,4,0,false><<<dim3(Kn/64, Bn/64), 256>>>(
        xin, U, nullptr, 0, hU, Bn, Kn, Dn);

    einsum_k<<<Bn/4, 256>>>(hU, s, h2);

    gemm_k<128,128,16,8,8,2,true><<<dim3(Dn/128, Bn/128), 256>>>(
        h2, V, s, SN, xout, Bn, Dn, Kn);
}

extern "C" void kernel_launch(void* const* d_in, const int* in_sizes, int n_in,
                              void* d_out, int out_size)
{
    const float* x    = (const float*)d_in[0];
    const float* Wout = (const float*)d_in[19];
    const float* bout = (const float*)d_in[20];

    float *h1, *s, *hU, *h2, *x1, *x2;
    cudaGetSymbolAddress((void**)&h1, g_h1);
    cudaGetSymbolAddress((void**)&s,  g_s);
    cudaGetSymbolAddress((void**)&hU, g_hU);
    cudaGetSymbolAddress((void**)&h2, g_h2);
    cudaGetSymbolAddress((void**)&x1, g_x1);
    cudaGetSymbolAddress((void**)&x2, g_x2);

    const float* U1  = (const float*)d_in[1];
    const float* V1  = (const float*)d_in[2];
    const float* W11 = (const float*)d_in[3];
    const float* b11 = (const float*)d_in[4];
    const float* W21 = (const float*)d_in[5];
    const float* b21 = (const float*)d_in[6];

    const float* U2  = (const float*)d_in[7];
    const float* V2  = (const float*)d_in[8];
    const float* W12 = (const float*)d_in[9];
    const float* b12 = (const float*)d_in[10];
    const float* W22 = (const float*)d_in[11];
    const float* b22 = (const float*)d_in[12];

    const float* U3  = (const float*)d_in[13];
    const float* V3  = (const float*)d_in[14];
    const float* W13 = (const float*)d_in[15];
    const float* b13 = (const float*)d_in[16];
    const float* W23 = (const float*)d_in[17];
    const float* b23 = (const float*)d_in[18];

    run_layer(x,  U1, V1, W11, b11, W21, b21, h1, s, hU, h2, x1);
    run_layer(x1, U2, V2, W12, b12, W22, b22, h1, s, hU, h2, x2);
    run_layer(x2, U3, V3, W13, b13, W23, b23, h1, s, hU, h2, x1);

    // 8192 rows, 1 warp/row, 8 warps per 256-thread block -> 1024 blocks
    outproj_k<<<Bn/8, 256>>>(x1, Wout, bout, (float*)d_out);
}